// round 8
// baseline (speedup 1.0000x reference)
#include <cuda_runtime.h>
#include <stdint.h>
#include <math.h>

// ---------------- problem constants ----------------
#define B_  32
#define S_  4096
#define D_  512
#define H_  512
#define M_  (B_ * S_)

#define SPLIT 32
#define S_PER_SPLIT 128

// gemm_e tiling (int8 IMMA, 3-plane-product scheme)
#define MT   64            // M rows per CTA
#define NCH  64            // N chunk
#define KCH  128           // K elems per B stage
#define NSTG 32            // (512/NCH)*(512/KCH)
#define APITCH 528u        // A row pitch bytes (512 s8 + 16 pad)
#define BPITCH 144u        // B row pitch bytes (128 s8 + 16 pad)
#define A0_OFF  0u
#define A1_OFF  33792u           // 64*528
#define B_OFF   67584u
#define B_HALF  9216u            // 64*144 (one plane, one stage)
#define B_STG   18432u           // both planes
#define T_OFF   104448u          // B_OFF + 2*B_STG
#define V_OFF   106496u
#define SB_OFF  108544u
#define SA_OFF  110592u          // 64 floats (row scales)
#define SAI_OFF 110848u          // 64 floats (inverse row scales)
#define E_OFF   111104u
#define SMEM_TOTAL 112128

// ---------------- device scratch ----------------
__device__ float g_t[B_ * H_];
__device__ float g_e[B_ * S_];
__device__ float g_ctx[B_ * SPLIT * D_];
__device__ int8_t g_wb0[H_ * D_];   // Ws hi plane (row h, k contiguous)
__device__ int8_t g_wb1[H_ * D_];   // Ws lo plane (residual * 128)
__device__ float  g_sb[H_];         // per-row scales

// ---------------- helpers ----------------
__device__ __forceinline__ uint32_t smem_u32(const void* p) {
    uint32_t a;
    asm("{ .reg .u64 t; cvta.to.shared.u64 t, %1; cvt.u32.u64 %0, t; }" : "=r"(a) : "l"(p));
    return a;
}
__device__ __forceinline__ void cp16(uint32_t dst, const void* src) {
    asm volatile("cp.async.cg.shared.global [%0], [%1], 16;" :: "r"(dst), "l"(src));
}
#define CP_COMMIT() asm volatile("cp.async.commit_group;" ::: "memory")
#define CP_WAIT(n)  asm volatile("cp.async.wait_group %0;" :: "n"(n) : "memory")

#define LDSM4(r0, r1, r2, r3, addr) \
    asm volatile("ldmatrix.sync.aligned.m8n8.x4.shared.b16 {%0,%1,%2,%3}, [%4];" \
                 : "=r"(r0), "=r"(r1), "=r"(r2), "=r"(r3) : "r"(addr))

#define IMMA(c0, c1, c2, c3, a0, a1, a2, a3, b0, b1) \
    asm volatile("mma.sync.aligned.m16n8k32.row.col.s32.s8.s8.s32 " \
                 "{%0,%1,%2,%3}, {%4,%5,%6,%7}, {%8,%9}, {%0,%1,%2,%3};" \
                 : "+r"(c0), "+r"(c1), "+r"(c2), "+r"(c3) \
                 : "r"(a0), "r"(a1), "r"(a2), "r"(a3), "r"(b0), "r"(b1))

__device__ __forceinline__ uint32_t pack4_s8(int a, int b, int c, int d) {
    return (uint32_t)(a & 0xFF) | ((uint32_t)(b & 0xFF) << 8) |
           ((uint32_t)(c & 0xFF) << 16) | ((uint32_t)(d & 0xFF) << 24);
}

// quantize one float given inv scale -> (hi, lo) int8 pair
__device__ __forceinline__ void quant2(float v, float inv, int& q0, int& q1) {
    float x = v * inv;
    q0 = __float2int_rn(x);
    q1 = __float2int_rn(128.0f * (x - (float)q0));
}

// ---------------- K0: quantize Ws rows to s8 hi/lo with per-row scale --------
__global__ __launch_bounds__(128) void wquant_kernel(const float* __restrict__ W) {
    __shared__ float wmax[4];
    __shared__ float sbv;
    const int h = blockIdx.x;
    const int t = threadIdx.x;
    const float4 v = *(const float4*)(W + (size_t)h * (2 * D_) + D_ + t * 4);
    float m = fmaxf(fmaxf(fabsf(v.x), fabsf(v.y)), fmaxf(fabsf(v.z), fabsf(v.w)));
#pragma unroll
    for (int o = 16; o >= 1; o >>= 1) m = fmaxf(m, __shfl_xor_sync(0xffffffffu, m, o));
    if ((t & 31) == 0) wmax[t >> 5] = m;
    __syncthreads();
    float mall = fmaxf(fmaxf(wmax[0], wmax[1]), fmaxf(wmax[2], wmax[3]));
    mall = fmaxf(mall, 1e-30f);
    if (t == 0) { g_sb[h] = mall / 127.0f; sbv = 127.0f / mall; }
    __syncthreads();
    const float inv = sbv;
    int q0[4], q1[4];
    quant2(v.x, inv, q0[0], q1[0]);
    quant2(v.y, inv, q0[1], q1[1]);
    quant2(v.z, inv, q0[2], q1[2]);
    quant2(v.w, inv, q0[3], q1[3]);
    ((uint32_t*)g_wb0)[h * 128 + t] = pack4_s8(q0[0], q0[1], q0[2], q0[3]);
    ((uint32_t*)g_wb1)[h * 128 + t] = pack4_s8(q1[0], q1[1], q1[2], q1[3]);
}

// ---------------- K1: t[b,h] = targ[b,:] . W[h,:D] (fp32) ----------------
__global__ __launch_bounds__(512) void t_kernel(const float* __restrict__ targ,
                                                const float* __restrict__ W) {
    __shared__ float ts[D_];
    int b = blockIdx.x, h = threadIdx.x;
    ts[h] = targ[b * D_ + h];
    __syncthreads();
    const float* wr = W + (size_t)h * (2 * D_);
    float s = 0.0f;
#pragma unroll 8
    for (int d = 0; d < D_; d += 4) {
        float4 w4 = *(const float4*)(wr + d);
        s += ts[d] * w4.x + ts[d + 1] * w4.y + ts[d + 2] * w4.z + ts[d + 3] * w4.w;
    }
    g_t[b * H_ + h] = s;
}

// ---------------- K2: int8 IMMA GEMM + tanh + V-dot -> g_e ----------------
__global__ __launch_bounds__(256, 1) void gemm_e_imma(const float* __restrict__ src,
                                                      const float* __restrict__ V) {
    extern __shared__ __align__(1024) char smem[];
    const int tid = threadIdx.x;
    const int lane = tid & 31;
    const int wid = tid >> 5;
    const int m_base = blockIdx.x * MT;
    const int b = blockIdx.x >> 6;                 // 64 CTAs per batch

    float* ts = (float*)(smem + T_OFF);
    float* vs = (float*)(smem + V_OFF);
    float* sbs = (float*)(smem + SB_OFF);
    float* sas = (float*)(smem + SA_OFF);
    float* sai = (float*)(smem + SAI_OFF);
    float* e_sm = (float*)(smem + E_OFF);
    const uint32_t sb = smem_u32(smem);

    for (int i = tid; i < 512; i += 256) {
        ts[i] = g_t[b * H_ + i];
        vs[i] = V[i];
        sbs[i] = g_sb[i];
    }

    const char* GB0 = (const char*)g_wb0;
    const char* GB1 = (const char*)g_wb1;

    // ---- issue B stage 0 (nc=0, ks=0): 1024 x 16B (both planes) ----
    {
        const uint32_t d0 = sb + B_OFF;
#pragma unroll
        for (int r = 0; r < 4; ++r) {
            int i = tid + r * 256;                 // 0..1023
            int half = i >> 9, j = i & 511;
            int n = j >> 3, c8 = j & 7;
            const char* srcp = (half ? GB1 : GB0) + (size_t)n * 512 + (size_t)c8 * 16;
            cp16(d0 + (uint32_t)half * B_HALF + (uint32_t)n * BPITCH + (uint32_t)c8 * 16, srcp);
        }
        CP_COMMIT();
    }

    // ---- A row maxes (64 rows): 4 threads per row ----
    const float* Ab = src + (size_t)m_base * D_;
    {
        const int row = tid >> 2;
        const int q = tid & 3;
        const float* p = Ab + (size_t)row * D_ + q * 128;
        float m = 0.0f;
#pragma unroll 8
        for (int i = 0; i < 32; ++i) {
            float4 v = *(const float4*)(p + i * 4);
            m = fmaxf(m, fmaxf(fmaxf(fabsf(v.x), fabsf(v.y)), fmaxf(fabsf(v.z), fabsf(v.w))));
        }
        m = fmaxf(m, __shfl_xor_sync(0xffffffffu, m, 1));
        m = fmaxf(m, __shfl_xor_sync(0xffffffffu, m, 2));
        m = fmaxf(m, 1e-30f);
        if (q == 0) { sas[row] = m / 127.0f; sai[row] = 127.0f / m; }
    }
    __syncthreads();

    // ---- stage A quantized to two s8 planes (FULL 64x512 coverage) ----
    for (int i = tid; i < 8192; i += 256) {        // 8192 float4 = 64 rows x 128
        int row = i >> 7;
        int c4 = (i & 127) << 2;                   // element offset 0..508
        float4 v = *(const float4*)(Ab + (size_t)row * D_ + c4);
        const float inv = sai[row];
        int q0[4], q1[4];
        quant2(v.x, inv, q0[0], q1[0]);
        quant2(v.y, inv, q0[1], q1[1]);
        quant2(v.z, inv, q0[2], q1[2]);
        quant2(v.w, inv, q0[3], q1[3]);
        uint32_t off = (uint32_t)row * APITCH + (uint32_t)c4;
        *(uint32_t*)(smem + A0_OFF + off) = pack4_s8(q0[0], q0[1], q0[2], q0[3]);
        *(uint32_t*)(smem + A1_OFF + off) = pack4_s8(q1[0], q1[1], q1[2], q1[3]);
    }

    const int wm = wid >> 2;                       // 0..1
    const int wn = wid & 3;                        // 0..3
    const int g = lane >> 2;
    const int c2 = (lane & 3) * 2;

    // A ldmatrix lane address: rows (lane&15), k-halves via lane>>4 (16B)
    const uint32_t a_row  = (uint32_t)(wm * 32 + (lane & 15));
    const uint32_t a_koff = (uint32_t)((lane >> 4) * 16);
    const uint32_t a0_base = sb + A0_OFF + a_row * APITCH + a_koff;
    const uint32_t a1_base = sb + A1_OFF + a_row * APITCH + a_koff;

    // B ldmatrix lane address: n sub-tiles via lane>>4, k-halves via (lane>>3)&1
    const uint32_t b_row  = (uint32_t)(wn * 16 + ((lane >> 4) & 1) * 8 + (lane & 7));
    const uint32_t b_koff = (uint32_t)(((lane >> 3) & 1) * 16);

    float e_acc[4] = {0.f, 0.f, 0.f, 0.f};
    int acc00[2][2][4];
    int acc01[2][2][4];

    for (int s = 0; s < NSTG; ++s) {
        const int nc = s >> 2;
        const int ks = s & 3;
        const int buf = s & 1;

        if (s + 1 < NSTG) {
            const int nc1 = (s + 1) >> 2;
            const int ks1 = (s + 1) & 3;
            const uint32_t d1 = sb + B_OFF + (uint32_t)(buf ^ 1) * B_STG;
            const size_t gbase = (size_t)nc1 * NCH * 512 + (size_t)ks1 * 128;
#pragma unroll
            for (int r = 0; r < 4; ++r) {
                int i = tid + r * 256;
                int half = i >> 9, j = i & 511;
                int n = j >> 3, c8 = j & 7;
                const char* srcp = (half ? GB1 : GB0) + gbase + (size_t)n * 512 + (size_t)c8 * 16;
                cp16(d1 + (uint32_t)half * B_HALF + (uint32_t)n * BPITCH + (uint32_t)c8 * 16, srcp);
            }
            CP_COMMIT();
            CP_WAIT(1);
        } else {
            CP_WAIT(0);
        }
        __syncthreads();

        if (ks == 0) {
#pragma unroll
            for (int i = 0; i < 2; ++i)
#pragma unroll
                for (int j = 0; j < 2; ++j)
#pragma unroll
                    for (int r = 0; r < 4; ++r) { acc00[i][j][r] = 0; acc01[i][j][r] = 0; }
        }

        const uint32_t b_hi_base = sb + B_OFF + (uint32_t)buf * B_STG + b_row * BPITCH + b_koff;
        const uint32_t b_lo_base = b_hi_base + B_HALF;
        const uint32_t a_kchunk = (uint32_t)(ks * KCH);    // bytes (1B/elem)

#pragma unroll
        for (int kk = 0; kk < 4; ++kk) {
            const uint32_t kb = (uint32_t)kk * 32;
            uint32_t a0f[2][4], a1f[2][4], bh[4], bl[4];
            LDSM4(a0f[0][0], a0f[0][1], a0f[0][2], a0f[0][3], a0_base + a_kchunk + kb);
            LDSM4(a0f[1][0], a0f[1][1], a0f[1][2], a0f[1][3], a0_base + a_kchunk + kb + 16u * APITCH);
            LDSM4(a1f[0][0], a1f[0][1], a1f[0][2], a1f[0][3], a1_base + a_kchunk + kb);
            LDSM4(a1f[1][0], a1f[1][1], a1f[1][2], a1f[1][3], a1_base + a_kchunk + kb + 16u * APITCH);
            LDSM4(bh[0], bh[1], bh[2], bh[3], b_hi_base + kb);
            LDSM4(bl[0], bl[1], bl[2], bl[3], b_lo_base + kb);

#pragma unroll
            for (int mt = 0; mt < 2; ++mt) {
                // S00 = a0*b0
                IMMA(acc00[mt][0][0], acc00[mt][0][1], acc00[mt][0][2], acc00[mt][0][3],
                     a0f[mt][0], a0f[mt][1], a0f[mt][2], a0f[mt][3], bh[0], bh[1]);
                IMMA(acc00[mt][1][0], acc00[mt][1][1], acc00[mt][1][2], acc00[mt][1][3],
                     a0f[mt][0], a0f[mt][1], a0f[mt][2], a0f[mt][3], bh[2], bh[3]);
                // S01 = a0*b1 + a1*b0 (shared accumulator)
                IMMA(acc01[mt][0][0], acc01[mt][0][1], acc01[mt][0][2], acc01[mt][0][3],
                     a0f[mt][0], a0f[mt][1], a0f[mt][2], a0f[mt][3], bl[0], bl[1]);
                IMMA(acc01[mt][1][0], acc01[mt][1][1], acc01[mt][1][2], acc01[mt][1][3],
                     a0f[mt][0], a0f[mt][1], a0f[mt][2], a0f[mt][3], bl[2], bl[3]);
                IMMA(acc01[mt][0][0], acc01[mt][0][1], acc01[mt][0][2], acc01[mt][0][3],
                     a1f[mt][0], a1f[mt][1], a1f[mt][2], a1f[mt][3], bh[0], bh[1]);
                IMMA(acc01[mt][1][0], acc01[mt][1][1], acc01[mt][1][2], acc01[mt][1][3],
                     a1f[mt][0], a1f[mt][1], a1f[mt][2], a1f[mt][3], bh[2], bh[3]);
            }
        }
        __syncthreads();

        if (ks == 3) {
            // epilogue: e += V * tanh(sa*sb*(S00 + S01/128) + t)
#pragma unroll
            for (int mt = 0; mt < 2; ++mt) {
                const int row01 = wm * 32 + mt * 16 + g;
                const float sa0 = sas[row01];
                const float sa1 = sas[row01 + 8];
#pragma unroll
                for (int nt = 0; nt < 2; ++nt) {
                    const int n0 = nc * NCH + wn * 16 + nt * 8 + c2;
                    const float t0 = ts[n0], t1 = ts[n0 + 1];
                    const float v0 = vs[n0], v1 = vs[n0 + 1];
                    const float sb0 = sbs[n0], sb1 = sbs[n0 + 1];
#pragma unroll
                    for (int r = 0; r < 4; ++r) {
                        const float tv = (r & 1) ? t1 : t0;
                        const float vv = (r & 1) ? v1 : v0;
                        const float sc = ((r < 2) ? sa0 : sa1) * ((r & 1) ? sb1 : sb0);
                        float p = (float)acc00[mt][nt][r] +
                                  (float)acc01[mt][nt][r] * 0.0078125f;
                        float x = fmaf(sc, p, tv);
                        float ex = __expf(2.0f * x);
                        float th = 1.0f - __fdividef(2.0f, ex + 1.0f);
                        e_acc[mt * 2 + (r >> 1)] = fmaf(vv, th, e_acc[mt * 2 + (r >> 1)]);
                    }
                }
            }
        }
    }

    // reduce e over the 4 lanes sharing a row
#pragma unroll
    for (int j = 0; j < 4; ++j) {
        e_acc[j] += __shfl_xor_sync(0xffffffffu, e_acc[j], 1);
        e_acc[j] += __shfl_xor_sync(0xffffffffu, e_acc[j], 2);
    }
    if ((lane & 3) == 0) {
#pragma unroll
        for (int j = 0; j < 4; ++j) {
            int row = wm * 32 + (j >> 1) * 16 + (j & 1) * 8 + g;
            e_sm[wn * 64 + row] = e_acc[j];
        }
    }
    __syncthreads();
    if (tid < MT) {
        float s = e_sm[tid] + e_sm[64 + tid] + e_sm[128 + tid] + e_sm[192 + tid];
        g_e[m_base + tid] = s;
    }
}

// ---------------- K3: softmax ----------------
__global__ __launch_bounds__(256) void softmax_kernel(const float* __restrict__ mask,
                                                      float* __restrict__ out_att) {
    const int b = blockIdx.x;
    const int tid = threadIdx.x;
    const float* e = g_e + (size_t)b * S_;
    __shared__ float red[8];

    float vals[16];
    float mx = -1e30f;
#pragma unroll
    for (int i = 0; i < 16; ++i) {
        vals[i] = e[tid + i * 256];
        mx = fmaxf(mx, vals[i]);
    }
#pragma unroll
    for (int o = 16; o >= 1; o >>= 1) mx = fmaxf(mx, __shfl_xor_sync(0xffffffffu, mx, o));
    if ((tid & 31) == 0) red[tid >> 5] = mx;
    __syncthreads();
    float M = red[0];
#pragma unroll
    for (int i = 1; i < 8; ++i) M = fmaxf(M, red[i]);
    __syncthreads();

    float sum = 0.0f;
#pragma unroll
    for (int i = 0; i < 16; ++i) {
        vals[i] = expf(vals[i] - M);
        sum += vals[i];
    }
#pragma unroll
    for (int o = 16; o >= 1; o >>= 1) sum += __shfl_xor_sync(0xffffffffu, sum, o);
    if ((tid & 31) == 0) red[tid >> 5] = sum;
    __syncthreads();
    float Ssum = 0.0f;
#pragma unroll
    for (int i = 0; i < 8; ++i) Ssum += red[i];

    const float inv = 1.0f / Ssum;
    const float* mrow = mask + (size_t)b * S_;
    float* orow = out_att + (size_t)b * S_;
#pragma unroll
    for (int i = 0; i < 16; ++i) {
        int s = tid + i * 256;
        orow[s] = vals[i] * inv * mrow[s];
    }
}

// ---------------- K4: ctx partials ----------------
__global__ __launch_bounds__(512) void ctx_partial_kernel(const float* __restrict__ src,
                                                          const float* __restrict__ att) {
    __shared__ float aw[S_PER_SPLIT];
    const int b = blockIdx.x;
    const int sp = blockIdx.y;
    const int tid = threadIdx.x;
    if (tid < S_PER_SPLIT) aw[tid] = att[(size_t)b * S_ + sp * S_PER_SPLIT + tid];
    __syncthreads();

    const float* p = src + ((size_t)b * S_ + (size_t)sp * S_PER_SPLIT) * D_ + tid;
    float a0 = 0.f, a1 = 0.f, a2 = 0.f, a3 = 0.f;
#pragma unroll 4
    for (int s = 0; s < S_PER_SPLIT; s += 4) {
        a0 = fmaf(aw[s + 0], p[(size_t)(s + 0) * D_], a0);
        a1 = fmaf(aw[s + 1], p[(size_t)(s + 1) * D_], a1);
        a2 = fmaf(aw[s + 2], p[(size_t)(s + 2) * D_], a2);
        a3 = fmaf(aw[s + 3], p[(size_t)(s + 3) * D_], a3);
    }
    g_ctx[((size_t)b * SPLIT + sp) * D_ + tid] = (a0 + a1) + (a2 + a3);
}

// ---------------- K5: reduce + residual ----------------
__global__ __launch_bounds__(512) void reduce_kernel(const float* __restrict__ targ,
                                                     float* __restrict__ out_hidden) {
    const int b = blockIdx.x;
    const int d = threadIdx.x;
    float s = targ[b * D_ + d];
#pragma unroll
    for (int sp = 0; sp < SPLIT; ++sp) s += g_ctx[((size_t)b * SPLIT + sp) * D_ + d];
    out_hidden[b * D_ + d] = s;
}

// ---------------- launcher ----------------
extern "C" void kernel_launch(void* const* d_in, const int* in_sizes, int n_in,
                              void* d_out, int out_size) {
    const float* targ = (const float*)d_in[0];
    const float* src  = (const float*)d_in[1];
    const float* mask = (const float*)d_in[2];
    const float* W    = (const float*)d_in[3];
    const float* V    = (const float*)d_in[4];

    float* out = (float*)d_out;
    float* out_att    = out;
    float* out_hidden = out + B_ * S_;

    cudaFuncSetAttribute(gemm_e_imma, cudaFuncAttributeMaxDynamicSharedMemorySize, SMEM_TOTAL);

    wquant_kernel<<<H_, 128>>>(W);
    t_kernel<<<B_, D_>>>(targ, W);
    gemm_e_imma<<<M_ / MT, 256, SMEM_TOTAL>>>(src, V);
    softmax_kernel<<<B_, 256>>>(mask, out_att);
    dim3 g4(B_, SPLIT);
    ctx_partial_kernel<<<g4, D_>>>(src, out_att);
    reduce_kernel<<<B_, D_>>>(targ, out_hidden);
}

// round 9
// speedup vs baseline: 2.3432x; 2.3432x over previous
#include <cuda_runtime.h>
#include <cuda_fp16.h>
#include <stdint.h>
#include <math.h>

// ---------------- problem constants ----------------
#define B_  32
#define S_  4096
#define D_  512
#define H_  512
#define M_  (B_ * S_)

#define SPLIT 32
#define S_PER_SPLIT 128

// gemm_e tiling (R6 config; LO plane -> fp16 accumulators)
#define MT   64            // M rows per CTA
#define NCH  64            // N chunk
#define KCH  128           // K chunk (B staging)
#define NSTG 32            // (512/NCH) * (512/KCH)
#define LO_SCALE 2048.0f   // 2^11
#define INV_LO_SCALE (1.0f / 2048.0f)
#define APITCH 1040u       // A row pitch bytes (512 fp16 = 1024B + 16 pad)
#define BPITCH 272u        // B row pitch bytes (128 fp16 = 256B + 16 pad)
#define A_OFF   0u
#define B_OFF   66560u           // 64*1040
#define B_HALF  17408u           // 64*272
#define B_STG   34816u           // hi + lo per stage
#define T_OFF   136192u          // B_OFF + 2*B_STG
#define V_OFF   138240u
#define E_OFF   140288u
#define SMEM_TOTAL 141312

// ---------------- device scratch ----------------
__device__ float g_t[B_ * H_];
__device__ float g_e[B_ * S_];
__device__ float g_ctx[B_ * SPLIT * D_];
__device__ __half g_wsh[H_ * D_];   // Ws hi fp16 (row h, k contiguous)
__device__ __half g_wsl[H_ * D_];   // (Ws - hi) * 2^11, fp16

// ---------------- helpers ----------------
__device__ __forceinline__ uint32_t smem_u32(const void* p) {
    uint32_t a;
    asm("{ .reg .u64 t; cvta.to.shared.u64 t, %1; cvt.u32.u64 %0, t; }" : "=r"(a) : "l"(p));
    return a;
}
__device__ __forceinline__ uint32_t pack_h2(float a, float b) {
    __half2 h = __floats2half2_rn(a, b);
    return *(uint32_t*)&h;
}
__device__ __forceinline__ void cp16(uint32_t dst, const void* src) {
    asm volatile("cp.async.cg.shared.global [%0], [%1], 16;" :: "r"(dst), "l"(src));
}
#define CP_COMMIT() asm volatile("cp.async.commit_group;" ::: "memory")
#define CP_WAIT(n)  asm volatile("cp.async.wait_group %0;" :: "n"(n) : "memory")

#define LDSM4(r0, r1, r2, r3, addr) \
    asm volatile("ldmatrix.sync.aligned.m8n8.x4.shared.b16 {%0,%1,%2,%3}, [%4];" \
                 : "=r"(r0), "=r"(r1), "=r"(r2), "=r"(r3) : "r"(addr))

// fp32-accumulator HMMA (HI plane)
#define MMAH16816(c0, c1, c2, c3, a0, a1, a2, a3, b0, b1) \
    asm volatile("mma.sync.aligned.m16n8k16.row.col.f32.f16.f16.f32 " \
                 "{%0,%1,%2,%3}, {%4,%5,%6,%7}, {%8,%9}, {%0,%1,%2,%3};" \
                 : "+f"(c0), "+f"(c1), "+f"(c2), "+f"(c3) \
                 : "r"(a0), "r"(a1), "r"(a2), "r"(a3), "r"(b0), "r"(b1))

// fp16-accumulator HMMA (LO plane): D/C packed half2 x2
#define MMAF16ACC(d0, d1, a0, a1, a2, a3, b0, b1) \
    asm volatile("mma.sync.aligned.m16n8k16.row.col.f16.f16.f16.f16 " \
                 "{%0,%1}, {%2,%3,%4,%5}, {%6,%7}, {%0,%1};" \
                 : "+r"(d0), "+r"(d1) \
                 : "r"(a0), "r"(a1), "r"(a2), "r"(a3), "r"(b0), "r"(b1))

// ---------------- K0: split Ws into fp16 hi + scaled lo ----------------
__global__ __launch_bounds__(256) void wsplit_kernel(const float* __restrict__ W) {
    int idx = blockIdx.x * 256 + threadIdx.x;
    int h = idx >> 9, d = idx & 511;
    float w = W[h * (2 * D_) + D_ + d];
    __half hi = __float2half_rn(w);
    float lo = (w - __half2float(hi)) * LO_SCALE;
    g_wsh[idx] = hi;
    g_wsl[idx] = __float2half_rn(lo);
}

// ---------------- K1: t[b,h] = targ[b,:] . W[h,:D] (fp32) ----------------
__global__ __launch_bounds__(512) void t_kernel(const float* __restrict__ targ,
                                                const float* __restrict__ W) {
    __shared__ float ts[D_];
    int b = blockIdx.x, h = threadIdx.x;
    ts[h] = targ[b * D_ + h];
    __syncthreads();
    const float* wr = W + (size_t)h * (2 * D_);
    float s = 0.0f;
#pragma unroll 8
    for (int d = 0; d < D_; d += 4) {
        float4 w4 = *(const float4*)(wr + d);
        s += ts[d] * w4.x + ts[d + 1] * w4.y + ts[d + 2] * w4.z + ts[d + 3] * w4.w;
    }
    g_t[b * H_ + h] = s;
}

// ---------------- K2: fp16 2-term mma GEMM + tanh + V-dot ----------------
__global__ __launch_bounds__(256, 1) void gemm_e_mma(const float* __restrict__ src,
                                                     const float* __restrict__ V) {
    extern __shared__ __align__(1024) char smem[];
    const int tid = threadIdx.x;
    const int lane = tid & 31;
    const int wid = tid >> 5;
    const int m_base = blockIdx.x * MT;
    const int b = blockIdx.x >> 6;                 // 64 CTAs per batch

    float* ts = (float*)(smem + T_OFF);
    float* vs = (float*)(smem + V_OFF);
    float* e_sm = (float*)(smem + E_OFF);
    const uint32_t sb = smem_u32(smem);

    for (int i = tid; i < 512; i += 256) {
        ts[i] = g_t[b * H_ + i];
        vs[i] = V[i];
    }

    const char* GHB = (const char*)g_wsh;
    const char* GLB = (const char*)g_wsl;

    // ---- issue B stage 0 (nc=0, ks=0): 2048 x 16B (hi + lo) ----
    {
        const uint32_t d0 = sb + B_OFF;
#pragma unroll
        for (int r = 0; r < 8; ++r) {
            int i = tid + r * 256;                 // 0..2047
            int half = i >> 10, j = i & 1023;
            int n = j >> 4, c8 = j & 15;
            const char* srcp = (half ? GLB : GHB) + (size_t)n * 1024 + (size_t)c8 * 16;
            cp16(d0 + (uint32_t)half * B_HALF + (uint32_t)n * BPITCH + (uint32_t)c8 * 16, srcp);
        }
        CP_COMMIT();
    }

    // ---- stage A (64 x 512 fp32 -> fp16, resident single buffer) ----
    const float* Ab = src + (size_t)m_base * D_;
    for (int i = tid; i < 8192; i += 256) {
        int row = i >> 7;
        int c4 = (i & 127) << 2;
        float4 v = *(const float4*)(Ab + (size_t)row * D_ + c4);
        uint32_t off = (uint32_t)row * APITCH + (uint32_t)c4 * 2;
        *(uint2*)(smem + A_OFF + off) = make_uint2(pack_h2(v.x, v.y), pack_h2(v.z, v.w));
    }

    const int wm = wid >> 2;                       // 0..1
    const int wn = wid & 3;                        // 0..3
    const int g = lane >> 2;
    const int c2 = (lane & 3) * 2;

    const uint32_t a_row  = (uint32_t)(wm * 32 + (lane & 15));
    const uint32_t a_koff = (uint32_t)((lane >> 4) * 8);
    const uint32_t b_row  = (uint32_t)(wn * 16 + (lane & 7) + ((lane >> 4) & 1) * 8);
    const uint32_t b_koff = (uint32_t)(((lane >> 3) & 1) * 8);

    const uint32_t a_base = sb + A_OFF + a_row * APITCH + a_koff * 2;

    float e_acc[4] = {0.f, 0.f, 0.f, 0.f};
    float accH[2][2][4];
    uint32_t accL[2][2][2];                        // fp16 half2 pairs

    for (int s = 0; s < NSTG; ++s) {
        const int nc = s >> 2;
        const int ks = s & 3;
        const int buf = s & 1;

        if (s + 1 < NSTG) {
            const int nc1 = (s + 1) >> 2;
            const int ks1 = (s + 1) & 3;
            const uint32_t d1 = sb + B_OFF + (uint32_t)(buf ^ 1) * B_STG;
            const size_t gbase = (size_t)nc1 * NCH * 1024 + (size_t)ks1 * 256;
#pragma unroll
            for (int r = 0; r < 8; ++r) {
                int i = tid + r * 256;
                int half = i >> 10, j = i & 1023;
                int n = j >> 4, c8 = j & 15;
                const char* srcp = (half ? GLB : GHB) + gbase + (size_t)n * 1024 + (size_t)c8 * 16;
                cp16(d1 + (uint32_t)half * B_HALF + (uint32_t)n * BPITCH + (uint32_t)c8 * 16, srcp);
            }
            CP_COMMIT();
            CP_WAIT(1);
        } else {
            CP_WAIT(0);
        }
        __syncthreads();

        if (ks == 0) {
#pragma unroll
            for (int i = 0; i < 2; ++i)
#pragma unroll
                for (int j = 0; j < 2; ++j) {
#pragma unroll
                    for (int r = 0; r < 4; ++r) accH[i][j][r] = 0.f;
                    accL[i][j][0] = 0u; accL[i][j][1] = 0u;
                }
        }

        const uint32_t b_hi_base = sb + B_OFF + (uint32_t)buf * B_STG + b_row * BPITCH + b_koff * 2;
        const uint32_t b_lo_base = b_hi_base + B_HALF;
        const uint32_t a_kchunk = (uint32_t)(ks * KCH) * 2;

#pragma unroll
        for (int kk = 0; kk < 8; ++kk) {
            const uint32_t kb = (uint32_t)kk * 32;
            uint32_t a0[4], a1[4], bh[4], bl[4];
            LDSM4(a0[0], a0[1], a0[2], a0[3], a_base + a_kchunk + kb);
            LDSM4(a1[0], a1[1], a1[2], a1[3], a_base + a_kchunk + kb + 16u * APITCH);
            LDSM4(bh[0], bh[1], bh[2], bh[3], b_hi_base + kb);
            LDSM4(bl[0], bl[1], bl[2], bl[3], b_lo_base + kb);

            // HI plane: fp32 accumulators
            MMAH16816(accH[0][0][0], accH[0][0][1], accH[0][0][2], accH[0][0][3],
                      a0[0], a0[1], a0[2], a0[3], bh[0], bh[1]);
            MMAH16816(accH[0][1][0], accH[0][1][1], accH[0][1][2], accH[0][1][3],
                      a0[0], a0[1], a0[2], a0[3], bh[2], bh[3]);
            MMAH16816(accH[1][0][0], accH[1][0][1], accH[1][0][2], accH[1][0][3],
                      a1[0], a1[1], a1[2], a1[3], bh[0], bh[1]);
            MMAH16816(accH[1][1][0], accH[1][1][1], accH[1][1][2], accH[1][1][3],
                      a1[0], a1[1], a1[2], a1[3], bh[2], bh[3]);

            // LO plane: fp16 accumulators (contribution scaled by 2^-11 later)
            MMAF16ACC(accL[0][0][0], accL[0][0][1],
                      a0[0], a0[1], a0[2], a0[3], bl[0], bl[1]);
            MMAF16ACC(accL[0][1][0], accL[0][1][1],
                      a0[0], a0[1], a0[2], a0[3], bl[2], bl[3]);
            MMAF16ACC(accL[1][0][0], accL[1][0][1],
                      a1[0], a1[1], a1[2], a1[3], bl[0], bl[1]);
            MMAF16ACC(accL[1][1][0], accL[1][1][1],
                      a1[0], a1[1], a1[2], a1[3], bl[2], bl[3]);
        }
        __syncthreads();

        if (ks == 3) {
            // epilogue for this nc: e += V * tanh(accH + accL/2^11 + t)
#pragma unroll
            for (int mt = 0; mt < 2; ++mt) {
#pragma unroll
                for (int nt = 0; nt < 2; ++nt) {
                    const int n0 = nc * NCH + wn * 16 + nt * 8 + c2;
                    const float t0 = ts[n0], t1 = ts[n0 + 1];
                    const float v0 = vs[n0], v1 = vs[n0 + 1];
                    const __half2 hA = *(__half2*)&accL[mt][nt][0];   // row g:   cols c2, c2+1
                    const __half2 hB = *(__half2*)&accL[mt][nt][1];   // row g+8: cols c2, c2+1
                    const float lo[4] = {__half2float(hA.x), __half2float(hA.y),
                                         __half2float(hB.x), __half2float(hB.y)};
#pragma unroll
                    for (int r = 0; r < 4; ++r) {
                        const float tv = (r & 1) ? t1 : t0;
                        const float vv = (r & 1) ? v1 : v0;
                        float x = fmaf(lo[r], INV_LO_SCALE, accH[mt][nt][r]) + tv;
                        float ex = __expf(2.0f * x);
                        float th = 1.0f - __fdividef(2.0f, ex + 1.0f);
                        e_acc[mt * 2 + (r >> 1)] = fmaf(vv, th, e_acc[mt * 2 + (r >> 1)]);
                    }
                }
            }
        }
    }

    // reduce e over the 4 lanes sharing a row
#pragma unroll
    for (int j = 0; j < 4; ++j) {
        e_acc[j] += __shfl_xor_sync(0xffffffffu, e_acc[j], 1);
        e_acc[j] += __shfl_xor_sync(0xffffffffu, e_acc[j], 2);
    }
    if ((lane & 3) == 0) {
#pragma unroll
        for (int j = 0; j < 4; ++j) {
            int row = wm * 32 + (j >> 1) * 16 + (j & 1) * 8 + g;
            e_sm[wn * 64 + row] = e_acc[j];
        }
    }
    __syncthreads();
    if (tid < MT) {
        float s = e_sm[tid] + e_sm[64 + tid] + e_sm[128 + tid] + e_sm[192 + tid];
        g_e[m_base + tid] = s;
    }
}

// ---------------- K3: softmax ----------------
__global__ __launch_bounds__(256) void softmax_kernel(const float* __restrict__ mask,
                                                      float* __restrict__ out_att) {
    const int b = blockIdx.x;
    const int tid = threadIdx.x;
    const float* e = g_e + (size_t)b * S_;
    __shared__ float red[8];

    float vals[16];
    float mx = -1e30f;
#pragma unroll
    for (int i = 0; i < 16; ++i) {
        vals[i] = e[tid + i * 256];
        mx = fmaxf(mx, vals[i]);
    }
#pragma unroll
    for (int o = 16; o >= 1; o >>= 1) mx = fmaxf(mx, __shfl_xor_sync(0xffffffffu, mx, o));
    if ((tid & 31) == 0) red[tid >> 5] = mx;
    __syncthreads();
    float M = red[0];
#pragma unroll
    for (int i = 1; i < 8; ++i) M = fmaxf(M, red[i]);
    __syncthreads();

    float sum = 0.0f;
#pragma unroll
    for (int i = 0; i < 16; ++i) {
        vals[i] = expf(vals[i] - M);
        sum += vals[i];
    }
#pragma unroll
    for (int o = 16; o >= 1; o >>= 1) sum += __shfl_xor_sync(0xffffffffu, sum, o);
    if ((tid & 31) == 0) red[tid >> 5] = sum;
    __syncthreads();
    float Ssum = 0.0f;
#pragma unroll
    for (int i = 0; i < 8; ++i) Ssum += red[i];

    const float inv = 1.0f / Ssum;
    const float* mrow = mask + (size_t)b * S_;
    float* orow = out_att + (size_t)b * S_;
#pragma unroll
    for (int i = 0; i < 16; ++i) {
        int s = tid + i * 256;
        orow[s] = vals[i] * inv * mrow[s];
    }
}

// ---------------- K4: ctx partials ----------------
__global__ __launch_bounds__(512) void ctx_partial_kernel(const float* __restrict__ src,
                                                          const float* __restrict__ att) {
    __shared__ float aw[S_PER_SPLIT];
    const int b = blockIdx.x;
    const int sp = blockIdx.y;
    const int tid = threadIdx.x;
    if (tid < S_PER_SPLIT) aw[tid] = att[(size_t)b * S_ + sp * S_PER_SPLIT + tid];
    __syncthreads();

    const float* p = src + ((size_t)b * S_ + (size_t)sp * S_PER_SPLIT) * D_ + tid;
    float a0 = 0.f, a1 = 0.f, a2 = 0.f, a3 = 0.f;
#pragma unroll 4
    for (int s = 0; s < S_PER_SPLIT; s += 4) {
        a0 = fmaf(aw[s + 0], p[(size_t)(s + 0) * D_], a0);
        a1 = fmaf(aw[s + 1], p[(size_t)(s + 1) * D_], a1);
        a2 = fmaf(aw[s + 2], p[(size_t)(s + 2) * D_], a2);
        a3 = fmaf(aw[s + 3], p[(size_t)(s + 3) * D_], a3);
    }
    g_ctx[((size_t)b * SPLIT + sp) * D_ + tid] = (a0 + a1) + (a2 + a3);
}

// ---------------- K5: reduce + residual ----------------
__global__ __launch_bounds__(512) void reduce_kernel(const float* __restrict__ targ,
                                                     float* __restrict__ out_hidden) {
    const int b = blockIdx.x;
    const int d = threadIdx.x;
    float s = targ[b * D_ + d];
#pragma unroll
    for (int sp = 0; sp < SPLIT; ++sp) s += g_ctx[((size_t)b * SPLIT + sp) * D_ + d];
    out_hidden[b * D_ + d] = s;
}

// ---------------- launcher ----------------
extern "C" void kernel_launch(void* const* d_in, const int* in_sizes, int n_in,
                              void* d_out, int out_size) {
    const float* targ = (const float*)d_in[0];
    const float* src  = (const float*)d_in[1];
    const float* mask = (const float*)d_in[2];
    const float* W    = (const float*)d_in[3];
    const float* V    = (const float*)d_in[4];

    float* out = (float*)d_out;
    float* out_att    = out;
    float* out_hidden = out + B_ * S_;

    cudaFuncSetAttribute(gemm_e_mma, cudaFuncAttributeMaxDynamicSharedMemorySize, SMEM_TOTAL);

    wsplit_kernel<<<H_ * D_ / 256, 256>>>(W);
    t_kernel<<<B_, D_>>>(targ, W);
    gemm_e_mma<<<M_ / MT, 256, SMEM_TOTAL>>>(src, V);
    softmax_kernel<<<B_, 256>>>(mask, out_att);
    dim3 g4(B_, SPLIT);
    ctx_partial_kernel<<<g4, D_>>>(src, out_att);
    reduce_kernel<<<B_, D_>>>(targ, out_hidden);
}

// round 10
// speedup vs baseline: 4.0009x; 1.7075x over previous
#include <cuda_runtime.h>
#include <cuda_fp16.h>
#include <stdint.h>
#include <math.h>

// ---------------- problem constants ----------------
#define B_  32
#define S_  4096
#define D_  512
#define H_  512
#define M_  (B_ * S_)

#define SPLIT 32
#define S_PER_SPLIT 128

// gemm_e tiling (1-plane fp16)
#define MT   64            // M rows per CTA
#define NCH  64            // N chunk
#define KCH  128           // K chunk (B staging)
#define NSTG 32            // (512/NCH) * (512/KCH)
#define APITCH 1040u       // A row pitch bytes (512 fp16 = 1024B + 16 pad)
#define BPITCH 272u        // B row pitch bytes (128 fp16 = 256B + 16 pad)
#define A_OFF   0u
#define B_OFF   66560u           // 64*1040
#define B_STG   17408u           // 64*272, hi plane only
#define T_OFF   101376u          // B_OFF + 2*B_STG
#define V_OFF   103424u
#define E_OFF   105472u
#define SMEM_TOTAL 106496

// ---------------- device scratch ----------------
__device__ float g_t[B_ * H_];
__device__ float g_e[B_ * S_];
__device__ float g_ctx[B_ * SPLIT * D_];
__device__ __half g_wsh[H_ * D_];   // Ws fp16 (row h, k contiguous)

// ---------------- helpers ----------------
__device__ __forceinline__ uint32_t smem_u32(const void* p) {
    uint32_t a;
    asm("{ .reg .u64 t; cvta.to.shared.u64 t, %1; cvt.u32.u64 %0, t; }" : "=r"(a) : "l"(p));
    return a;
}
__device__ __forceinline__ uint32_t pack_h2(float a, float b) {
    __half2 h = __floats2half2_rn(a, b);
    return *(uint32_t*)&h;
}
__device__ __forceinline__ void cp16(uint32_t dst, const void* src) {
    asm volatile("cp.async.cg.shared.global [%0], [%1], 16;" :: "r"(dst), "l"(src));
}
#define CP_COMMIT() asm volatile("cp.async.commit_group;" ::: "memory")
#define CP_WAIT(n)  asm volatile("cp.async.wait_group %0;" :: "n"(n) : "memory")

#define LDSM4(r0, r1, r2, r3, addr) \
    asm volatile("ldmatrix.sync.aligned.m8n8.x4.shared.b16 {%0,%1,%2,%3}, [%4];" \
                 : "=r"(r0), "=r"(r1), "=r"(r2), "=r"(r3) : "r"(addr))

#define MMAH16816(c0, c1, c2, c3, a0, a1, a2, a3, b0, b1) \
    asm volatile("mma.sync.aligned.m16n8k16.row.col.f32.f16.f16.f32 " \
                 "{%0,%1,%2,%3}, {%4,%5,%6,%7}, {%8,%9}, {%0,%1,%2,%3};" \
                 : "+f"(c0), "+f"(c1), "+f"(c2), "+f"(c3) \
                 : "r"(a0), "r"(a1), "r"(a2), "r"(a3), "r"(b0), "r"(b1))

// ---------------- K0: convert Ws to fp16 ----------------
__global__ __launch_bounds__(256) void wsplit_kernel(const float* __restrict__ W) {
    int idx = blockIdx.x * 256 + threadIdx.x;
    int h = idx >> 9, d = idx & 511;
    float w = W[h * (2 * D_) + D_ + d];
    g_wsh[idx] = __float2half_rn(w);
}

// ---------------- K1: t[b,h] = targ[b,:] . W[h,:D] (fp32) ----------------
__global__ __launch_bounds__(512) void t_kernel(const float* __restrict__ targ,
                                                const float* __restrict__ W) {
    __shared__ float ts[D_];
    int b = blockIdx.x, h = threadIdx.x;
    ts[h] = targ[b * D_ + h];
    __syncthreads();
    const float* wr = W + (size_t)h * (2 * D_);
    float s = 0.0f;
#pragma unroll 8
    for (int d = 0; d < D_; d += 4) {
        float4 w4 = *(const float4*)(wr + d);
        s += ts[d] * w4.x + ts[d + 1] * w4.y + ts[d + 2] * w4.z + ts[d + 3] * w4.w;
    }
    g_t[b * H_ + h] = s;
}

// ---------------- K2: fp16 1-plane mma GEMM + tanh + V-dot ----------------
__global__ __launch_bounds__(256, 1) void gemm_e_mma(const float* __restrict__ src,
                                                     const float* __restrict__ V) {
    extern __shared__ __align__(1024) char smem[];
    const int tid = threadIdx.x;
    const int lane = tid & 31;
    const int wid = tid >> 5;
    const int m_base = blockIdx.x * MT;
    const int b = blockIdx.x >> 6;                 // 64 CTAs per batch

    float* ts = (float*)(smem + T_OFF);
    float* vs = (float*)(smem + V_OFF);
    float* e_sm = (float*)(smem + E_OFF);
    const uint32_t sb = smem_u32(smem);

    for (int i = tid; i < 512; i += 256) {
        ts[i] = g_t[b * H_ + i];
        vs[i] = V[i];
    }

    const char* GHB = (const char*)g_wsh;

    // ---- issue B stage 0 (nc=0, ks=0): 1024 x 16B ----
    {
        const uint32_t d0 = sb + B_OFF;
#pragma unroll
        for (int r = 0; r < 4; ++r) {
            int i = tid + r * 256;                 // 0..1023
            int n = i >> 4, c8 = i & 15;
            const char* srcp = GHB + (size_t)n * 1024 + (size_t)c8 * 16;
            cp16(d0 + (uint32_t)n * BPITCH + (uint32_t)c8 * 16, srcp);
        }
        CP_COMMIT();
    }

    // ---- stage A (64 x 512 fp32 -> fp16, resident single buffer) ----
    const float* Ab = src + (size_t)m_base * D_;
    for (int i = tid; i < 8192; i += 256) {
        int row = i >> 7;
        int c4 = (i & 127) << 2;
        float4 v = *(const float4*)(Ab + (size_t)row * D_ + c4);
        uint32_t off = (uint32_t)row * APITCH + (uint32_t)c4 * 2;
        *(uint2*)(smem + A_OFF + off) = make_uint2(pack_h2(v.x, v.y), pack_h2(v.z, v.w));
    }

    const int wm = wid >> 2;                       // 0..1
    const int wn = wid & 3;                        // 0..3
    const int g = lane >> 2;
    const int c2 = (lane & 3) * 2;

    const uint32_t a_row  = (uint32_t)(wm * 32 + (lane & 15));
    const uint32_t a_koff = (uint32_t)((lane >> 4) * 8);
    const uint32_t b_row  = (uint32_t)(wn * 16 + (lane & 7) + ((lane >> 4) & 1) * 8);
    const uint32_t b_koff = (uint32_t)(((lane >> 3) & 1) * 8);

    const uint32_t a_base = sb + A_OFF + a_row * APITCH + a_koff * 2;

    float e_acc[4] = {0.f, 0.f, 0.f, 0.f};
    float accH[2][2][4];

    for (int s = 0; s < NSTG; ++s) {
        const int nc = s >> 2;
        const int ks = s & 3;
        const int buf = s & 1;

        if (s + 1 < NSTG) {
            const int nc1 = (s + 1) >> 2;
            const int ks1 = (s + 1) & 3;
            const uint32_t d1 = sb + B_OFF + (uint32_t)(buf ^ 1) * B_STG;
            const size_t gbase = (size_t)nc1 * NCH * 1024 + (size_t)ks1 * 256;
#pragma unroll
            for (int r = 0; r < 4; ++r) {
                int i = tid + r * 256;
                int n = i >> 4, c8 = i & 15;
                const char* srcp = GHB + gbase + (size_t)n * 1024 + (size_t)c8 * 16;
                cp16(d1 + (uint32_t)n * BPITCH + (uint32_t)c8 * 16, srcp);
            }
            CP_COMMIT();
            CP_WAIT(1);
        } else {
            CP_WAIT(0);
        }
        __syncthreads();

        if (ks == 0) {
#pragma unroll
            for (int i = 0; i < 2; ++i)
#pragma unroll
                for (int j = 0; j < 2; ++j)
#pragma unroll
                    for (int r = 0; r < 4; ++r) accH[i][j][r] = 0.f;
        }

        const uint32_t b_hi_base = sb + B_OFF + (uint32_t)buf * B_STG + b_row * BPITCH + b_koff * 2;
        const uint32_t a_kchunk = (uint32_t)(ks * KCH) * 2;

#pragma unroll
        for (int kk = 0; kk < 8; ++kk) {
            const uint32_t kb = (uint32_t)kk * 32;
            uint32_t a0[4], a1[4], bh[4];
            LDSM4(a0[0], a0[1], a0[2], a0[3], a_base + a_kchunk + kb);
            LDSM4(a1[0], a1[1], a1[2], a1[3], a_base + a_kchunk + kb + 16u * APITCH);
            LDSM4(bh[0], bh[1], bh[2], bh[3], b_hi_base + kb);

            MMAH16816(accH[0][0][0], accH[0][0][1], accH[0][0][2], accH[0][0][3],
                      a0[0], a0[1], a0[2], a0[3], bh[0], bh[1]);
            MMAH16816(accH[0][1][0], accH[0][1][1], accH[0][1][2], accH[0][1][3],
                      a0[0], a0[1], a0[2], a0[3], bh[2], bh[3]);
            MMAH16816(accH[1][0][0], accH[1][0][1], accH[1][0][2], accH[1][0][3],
                      a1[0], a1[1], a1[2], a1[3], bh[0], bh[1]);
            MMAH16816(accH[1][1][0], accH[1][1][1], accH[1][1][2], accH[1][1][3],
                      a1[0], a1[1], a1[2], a1[3], bh[2], bh[3]);
        }
        __syncthreads();

        if (ks == 3) {
            // epilogue for this nc: e += V * tanh(accH + t)
#pragma unroll
            for (int mt = 0; mt < 2; ++mt) {
#pragma unroll
                for (int nt = 0; nt < 2; ++nt) {
                    const int n0 = nc * NCH + wn * 16 + nt * 8 + c2;
                    const float t0 = ts[n0], t1 = ts[n0 + 1];
                    const float v0 = vs[n0], v1 = vs[n0 + 1];
#pragma unroll
                    for (int r = 0; r < 4; ++r) {
                        const float tv = (r & 1) ? t1 : t0;
                        const float vv = (r & 1) ? v1 : v0;
                        float x = accH[mt][nt][r] + tv;
                        float ex = __expf(2.0f * x);
                        float th = 1.0f - __fdividef(2.0f, ex + 1.0f);
                        e_acc[mt * 2 + (r >> 1)] = fmaf(vv, th, e_acc[mt * 2 + (r >> 1)]);
                    }
                }
            }
        }
    }

    // reduce e over the 4 lanes sharing a row
#pragma unroll
    for (int j = 0; j < 4; ++j) {
        e_acc[j] += __shfl_xor_sync(0xffffffffu, e_acc[j], 1);
        e_acc[j] += __shfl_xor_sync(0xffffffffu, e_acc[j], 2);
    }
    if ((lane & 3) == 0) {
#pragma unroll
        for (int j = 0; j < 4; ++j) {
            int row = wm * 32 + (j >> 1) * 16 + (j & 1) * 8 + g;
            e_sm[wn * 64 + row] = e_acc[j];
        }
    }
    __syncthreads();
    if (tid < MT) {
        float s = e_sm[tid] + e_sm[64 + tid] + e_sm[128 + tid] + e_sm[192 + tid];
        g_e[m_base + tid] = s;
    }
}

// ---------------- K3: softmax ----------------
__global__ __launch_bounds__(256) void softmax_kernel(const float* __restrict__ mask,
                                                      float* __restrict__ out_att) {
    const int b = blockIdx.x;
    const int tid = threadIdx.x;
    const float* e = g_e + (size_t)b * S_;
    __shared__ float red[8];

    float vals[16];
    float mx = -1e30f;
#pragma unroll
    for (int i = 0; i < 16; ++i) {
        vals[i] = e[tid + i * 256];
        mx = fmaxf(mx, vals[i]);
    }
#pragma unroll
    for (int o = 16; o >= 1; o >>= 1) mx = fmaxf(mx, __shfl_xor_sync(0xffffffffu, mx, o));
    if ((tid & 31) == 0) red[tid >> 5] = mx;
    __syncthreads();
    float M = red[0];
#pragma unroll
    for (int i = 1; i < 8; ++i) M = fmaxf(M, red[i]);
    __syncthreads();

    float sum = 0.0f;
#pragma unroll
    for (int i = 0; i < 16; ++i) {
        vals[i] = expf(vals[i] - M);
        sum += vals[i];
    }
#pragma unroll
    for (int o = 16; o >= 1; o >>= 1) sum += __shfl_xor_sync(0xffffffffu, sum, o);
    if ((tid & 31) == 0) red[tid >> 5] = sum;
    __syncthreads();
    float Ssum = 0.0f;
#pragma unroll
    for (int i = 0; i < 8; ++i) Ssum += red[i];

    const float inv = 1.0f / Ssum;
    const float* mrow = mask + (size_t)b * S_;
    float* orow = out_att + (size_t)b * S_;
#pragma unroll
    for (int i = 0; i < 16; ++i) {
        int s = tid + i * 256;
        orow[s] = vals[i] * inv * mrow[s];
    }
}

// ---------------- K4: ctx partials ----------------
__global__ __launch_bounds__(512) void ctx_partial_kernel(const float* __restrict__ src,
                                                          const float* __restrict__ att) {
    __shared__ float aw[S_PER_SPLIT];
    const int b = blockIdx.x;
    const int sp = blockIdx.y;
    const int tid = threadIdx.x;
    if (tid < S_PER_SPLIT) aw[tid] = att[(size_t)b * S_ + sp * S_PER_SPLIT + tid];
    __syncthreads();

    const float* p = src + ((size_t)b * S_ + (size_t)sp * S_PER_SPLIT) * D_ + tid;
    float a0 = 0.f, a1 = 0.f, a2 = 0.f, a3 = 0.f;
#pragma unroll 4
    for (int s = 0; s < S_PER_SPLIT; s += 4) {
        a0 = fmaf(aw[s + 0], p[(size_t)(s + 0) * D_], a0);
        a1 = fmaf(aw[s + 1], p[(size_t)(s + 1) * D_], a1);
        a2 = fmaf(aw[s + 2], p[(size_t)(s + 2) * D_], a2);
        a3 = fmaf(aw[s + 3], p[(size_t)(s + 3) * D_], a3);
    }
    g_ctx[((size_t)b * SPLIT + sp) * D_ + tid] = (a0 + a1) + (a2 + a3);
}

// ---------------- K5: reduce + residual ----------------
__global__ __launch_bounds__(512) void reduce_kernel(const float* __restrict__ targ,
                                                     float* __restrict__ out_hidden) {
    const int b = blockIdx.x;
    const int d = threadIdx.x;
    float s = targ[b * D_ + d];
#pragma unroll
    for (int sp = 0; sp < SPLIT; ++sp) s += g_ctx[((size_t)b * SPLIT + sp) * D_ + d];
    out_hidden[b * D_ + d] = s;
}

// ---------------- launcher ----------------
extern "C" void kernel_launch(void* const* d_in, const int* in_sizes, int n_in,
                              void* d_out, int out_size) {
    const float* targ = (const float*)d_in[0];
    const float* src  = (const float*)d_in[1];
    const float* mask = (const float*)d_in[2];
    const float* W    = (const float*)d_in[3];
    const float* V    = (const float*)d_in[4];

    float* out = (float*)d_out;
    float* out_att    = out;
    float* out_hidden = out + B_ * S_;

    cudaFuncSetAttribute(gemm_e_mma, cudaFuncAttributeMaxDynamicSharedMemorySize, SMEM_TOTAL);

    wsplit_kernel<<<H_ * D_ / 256, 256>>>(W);
    t_kernel<<<B_, D_>>>(targ, W);
    gemm_e_mma<<<M_ / MT, 256, SMEM_TOTAL>>>(src, V);
    softmax_kernel<<<B_, 256>>>(mask, out_att);
    dim3 g4(B_, SPLIT);
    ctx_partial_kernel<<<g4, D_>>>(src, out_att);
    reduce_kernel<<<B_, D_>>>(targ, out_hidden);
}